// round 15
// baseline (speedup 1.0000x reference)
#include <cuda_runtime.h>
#include <cuda_bf16.h>
#include <cstdint>
#include <math.h>

typedef unsigned long long ull;
typedef unsigned short u16;

#define MTOK 32768
#define EROWS 30522
#define KDIM  768
#define EELEM (EROWS * KDIM)
#define WELEM (512 * KDIM)

// ---------------- static scratch ----------------
__device__ float g_pre_wf[MTOK * 512];
__device__ float g_pre_wb[MTOK * 512];
__device__ float g_pre_sf[MTOK * 512];
__device__ float g_pre_sb[MTOK * 512];
__device__ float g_fo[MTOK * 256];
__device__ float g_fs[MTOK * 256];
__device__ u16 g_Eh[EELEM];
__device__ u16 g_El[EELEM];
__device__ u16 g_Wh[4 * WELEM];
__device__ u16 g_Wl[4 * WELEM];
__device__ u16 g_foh[MTOK * 256];
__device__ u16 g_fol[MTOK * 256];
__device__ u16 g_fsh[MTOK * 256];
__device__ u16 g_fsl[MTOK * 256];
__device__ u16 g_gWh[256 * 512];
__device__ u16 g_gWl[256 * 512];

// ---------------- helpers ----------------
__device__ __forceinline__ ull ffma2(ull a, ull b, ull c) {
    ull d; asm("fma.rn.f32x2 %0,%1,%2,%3;" : "=l"(d) : "l"(a), "l"(b), "l"(c)); return d;
}
__device__ __forceinline__ float2 unpack2(ull v) {
    float2 r; asm("mov.b64 {%0,%1},%2;" : "=f"(r.x), "=f"(r.y) : "l"(v)); return r;
}
__device__ __forceinline__ uint32_t smem_u32(const void* p) {
    uint32_t a;
    asm("{ .reg .u64 t; cvta.to.shared.u64 t, %1; cvt.u32.u64 %0, t; }" : "=r"(a) : "l"(p));
    return a;
}
__device__ __forceinline__ uint32_t ctarank() {
    uint32_t r; asm("mov.u32 %0, %%cluster_ctarank;" : "=r"(r)); return r;
}
__device__ __forceinline__ uint32_t mapa_u32(uint32_t addr, uint32_t rank) {
    uint32_t r; asm("mapa.shared::cluster.u32 %0, %1, %2;" : "=r"(r) : "r"(addr), "r"(rank)); return r;
}
__device__ __forceinline__ void mbar_init(uint32_t a, uint32_t cnt) {
    asm volatile("mbarrier.init.shared.b64 [%0], %1;" :: "r"(a), "r"(cnt) : "memory");
}
__device__ __forceinline__ void st_cluster_f32(uint32_t a, float v) {
    asm volatile("st.shared::cluster.f32 [%0], %1;" :: "r"(a), "f"(v) : "memory");
}
__device__ __forceinline__ void mbar_arrive_rel_cluster(uint32_t a) {
    asm volatile("mbarrier.arrive.release.cluster.shared::cluster.b64 _, [%0];" :: "r"(a) : "memory");
}
__device__ __forceinline__ void mbar_wait(uint32_t a, uint32_t parity) {
    asm volatile(
        "{\n\t.reg .pred P;\n\t"
        "WL_%=:\n\t"
        "mbarrier.try_wait.parity.acquire.cluster.shared::cta.b64 P, [%0], %1, 0x989680;\n\t"
        "@P bra.uni WD_%=;\n\t"
        "bra.uni WL_%=;\n\t"
        "WD_%=:\n\t}"
        :: "r"(a), "r"(parity) : "memory");
}
__device__ __forceinline__ void cluster_sync_() {
    asm volatile("barrier.cluster.arrive.aligned;" ::: "memory");
    asm volatile("barrier.cluster.wait.aligned;" ::: "memory");
}
__device__ __forceinline__ float sigm(float x) {
    return __fdividef(1.f, 1.f + __expf(-x));
}
__device__ __forceinline__ float tanh_fast(float x) {
    float ax = fabsf(x);
    float e = __expf(-2.f * ax);
    float t = __fdividef(1.f - e, 1.f + e);
    return copysignf(t, x);
}

// ---- Ampere-class tensor primitives ----
__device__ __forceinline__ void ldsm_x4(uint32_t& r0, uint32_t& r1, uint32_t& r2, uint32_t& r3,
                                        uint32_t addr) {
    asm volatile("ldmatrix.sync.aligned.m8n8.x4.shared.b16 {%0,%1,%2,%3}, [%4];"
                 : "=r"(r0), "=r"(r1), "=r"(r2), "=r"(r3) : "r"(addr));
}
__device__ __forceinline__ void mma_bf16(float* d, const uint32_t* a, const uint32_t* b) {
    asm volatile("mma.sync.aligned.m16n8k16.row.col.f32.bf16.bf16.f32 "
                 "{%0,%1,%2,%3}, {%4,%5,%6,%7}, {%8,%9}, {%0,%1,%2,%3};"
                 : "+f"(d[0]), "+f"(d[1]), "+f"(d[2]), "+f"(d[3])
                 : "r"(a[0]), "r"(a[1]), "r"(a[2]), "r"(a[3]), "r"(b[0]), "r"(b[1]));
}
__device__ __forceinline__ void cp_async16(uint32_t dst, const void* src) {
    asm volatile("cp.async.cg.shared.global [%0], [%1], 16;" :: "r"(dst), "l"(src) : "memory");
}
__device__ __forceinline__ void cp_commit() { asm volatile("cp.async.commit_group;" ::: "memory"); }
__device__ __forceinline__ void cp_wait1() { asm volatile("cp.async.wait_group 1;" ::: "memory"); }
__device__ __forceinline__ void cp_wait0() { asm volatile("cp.async.wait_group 0;" ::: "memory"); }

// ---------------- bf16 hi/lo split ----------------
__global__ void cvt_split_k(const float* __restrict__ x, u16* __restrict__ hi,
                            u16* __restrict__ lo, int n4)
{
    int i = blockIdx.x * blockDim.x + threadIdx.x;
    if (i >= n4) return;
    float4 v = __ldg((const float4*)x + i);
    __nv_bfloat16 h0 = __float2bfloat16(v.x), h1 = __float2bfloat16(v.y);
    __nv_bfloat16 h2 = __float2bfloat16(v.z), h3 = __float2bfloat16(v.w);
    __nv_bfloat16 l0 = __float2bfloat16(v.x - __bfloat162float(h0));
    __nv_bfloat16 l1 = __float2bfloat16(v.y - __bfloat162float(h1));
    __nv_bfloat16 l2 = __float2bfloat16(v.z - __bfloat162float(h2));
    __nv_bfloat16 l3 = __float2bfloat16(v.w - __bfloat162float(h3));
    ushort4 hv = {__bfloat16_as_ushort(h0), __bfloat16_as_ushort(h1),
                  __bfloat16_as_ushort(h2), __bfloat16_as_ushort(h3)};
    ushort4 lv = {__bfloat16_as_ushort(l0), __bfloat16_as_ushort(l1),
                  __bfloat16_as_ushort(l2), __bfloat16_as_ushort(l3)};
    *(ushort4*)(hi + 4 * i) = hv;
    *(ushort4*)(lo + 4 * i) = lv;
}

// ---------------- HMMA pre-activation GEMM (3-stage) ----------------
struct TcArgs {
    const int*   idx[4];
    const float* bias[4];
    float*       C[4];
};

#define STG 32768
#define MG_SMEM (1024 + 3 * STG)

__device__ __forceinline__ uint32_t swaddr(uint32_t base, int row, int chunk) {
    uint32_t off = (uint32_t)(row * 128 + chunk * 16);
    return base + (off ^ ((off >> 3) & 0x70));
}

__global__ __launch_bounds__(256, 2)
void mma_gemm(TcArgs args, const u16* __restrict__ Eh, const u16* __restrict__ El,
              const u16* __restrict__ Wh, const u16* __restrict__ Wl)
{
    extern __shared__ char sm[];
    const int tid = threadIdx.x, lid = tid & 31, wid = tid >> 5;
    const int n0 = blockIdx.x * 128, m0 = blockIdx.y * 128, z = blockIdx.z;
    const u16* Whz = Wh + (size_t)z * WELEM;
    const u16* Wlz = Wl + (size_t)z * WELEM;
    int* idx_sm = (int*)sm;
    if (tid < 128) idx_sm[tid] = __ldg(args.idx[z] + m0 + tid);
    __syncthreads();
    const uint32_t smb = smem_u32(sm);
    const int wm = wid & 3, wn = wid >> 2;

    const int ldrow = tid >> 1, ldh = tid & 1;
    const size_t a_gr = (size_t)idx_sm[ldrow] * KDIM + ldh * 32;
    const size_t b_gr = (size_t)(n0 + ldrow) * KDIM + ldh * 32;
    uint32_t adst[4], bdst[4];
#pragma unroll
    for (int s = 0; s < 4; s++) {
        adst[s] = swaddr(smb + 1024, ldrow, ldh * 4 + s);
        bdst[s] = swaddr(smb + 1024 + 16384, ldrow, ldh * 4 + s);
    }

    float d[2][8][4];
#pragma unroll
    for (int i = 0; i < 2; i++)
#pragma unroll
        for (int j = 0; j < 8; j++)
#pragma unroll
            for (int k = 0; k < 4; k++) d[i][j][k] = 0.f;

    auto issue = [&](int c, int buf) {
        const int p = c / 12, kbase = (c % 12) * 64;
        const u16* As = (p == 1) ? El : Eh;
        const u16* Bs = (p == 2) ? Wlz : Whz;
        const u16* as = As + a_gr + kbase;
        const u16* bs = Bs + b_gr + kbase;
        const uint32_t bo = (uint32_t)(buf * STG);
#pragma unroll
        for (int s = 0; s < 4; s++) cp_async16(adst[s] + bo, as + 8 * s);
#pragma unroll
        for (int s = 0; s < 4; s++) cp_async16(bdst[s] + bo, bs + 8 * s);
        cp_commit();
    };

    const int g8 = lid & 7, grp = lid >> 3;
    const int arow_off = g8 + ((grp & 1) << 3);
    const int acol_sel = grp >> 1;
    const int brow_off = g8 + ((grp >> 1) << 3);
    const int bcol_sel = grp & 1;

    issue(0, 0);
    issue(1, 1);

#pragma unroll 1
    for (int c = 0; c < 36; c++) {
        const int buf = c % 3;
        if (c < 34) cp_wait1(); else cp_wait0();
        __syncthreads();
        if (c + 2 < 36) issue(c + 2, (c + 2) % 3);
        const uint32_t abase = smb + 1024 + buf * STG;
        const uint32_t bbase = abase + 16384;
#pragma unroll
        for (int kt2 = 0; kt2 < 2; kt2++) {
            uint32_t a[2][2][4];
#pragma unroll
            for (int mt = 0; mt < 2; mt++)
#pragma unroll
                for (int kk = 0; kk < 2; kk++) {
                    int kt = 2 * kt2 + kk;
                    ldsm_x4(a[mt][kk][0], a[mt][kk][1], a[mt][kk][2], a[mt][kk][3],
                            swaddr(abase, wm * 32 + mt * 16 + arow_off, 2 * kt + acol_sel));
                }
#pragma unroll
            for (int nt = 0; nt < 4; nt++) {
                uint32_t b[2][4];
#pragma unroll
                for (int kk = 0; kk < 2; kk++) {
                    int kt = 2 * kt2 + kk;
                    ldsm_x4(b[kk][0], b[kk][1], b[kk][2], b[kk][3],
                            swaddr(bbase, wn * 64 + nt * 16 + brow_off, 2 * kt + bcol_sel));
                }
#pragma unroll
                for (int mt = 0; mt < 2; mt++)
#pragma unroll
                    for (int n8 = 0; n8 < 2; n8++)
#pragma unroll
                        for (int kk = 0; kk < 2; kk++)
                            mma_bf16(d[mt][nt * 2 + n8], a[mt][kk], &b[kk][n8 * 2]);
            }
        }
        __syncthreads();
    }

    const float* bias = args.bias[z];
    float* C = args.C[z];
#pragma unroll
    for (int mt = 0; mt < 2; mt++) {
        int r0 = m0 + wm * 32 + mt * 16 + (lid >> 2);
#pragma unroll
        for (int f = 0; f < 8; f++) {
            int n = n0 + wn * 64 + f * 8 + 2 * (lid & 3);
            float2 bv = *(const float2*)(bias + n);
            float2 o0 = {d[mt][f][0] + bv.x, d[mt][f][1] + bv.y};
            float2 o1 = {d[mt][f][2] + bv.x, d[mt][f][3] + bv.y};
            *(float2*)(C + (size_t)r0 * 512 + n) = o0;
            *(float2*)(C + (size_t)(r0 + 8) * 512 + n) = o1;
        }
    }
}

// ---------------- HMMA gate GEMM + sigmoid blend (3-stage) ----------------
__global__ __launch_bounds__(256, 2)
void gate_mma(const u16* __restrict__ foh, const u16* __restrict__ fol,
              const u16* __restrict__ fsh, const u16* __restrict__ fsl,
              const u16* __restrict__ gWh, const u16* __restrict__ gWl,
              const float* __restrict__ gb, float* __restrict__ out,
              const float* __restrict__ fo, const float* __restrict__ fs)
{
    extern __shared__ char sm[];
    const int tid = threadIdx.x, lid = tid & 31, wid = tid >> 5;
    const int n0 = blockIdx.x * 128, m0 = blockIdx.y * 128;
    const uint32_t smb = smem_u32(sm);
    const int wm = wid & 3, wn = wid >> 2;

    const int ldrow = tid >> 1, ldh = tid & 1;
    uint32_t adst[4], bdst[4];
#pragma unroll
    for (int s = 0; s < 4; s++) {
        adst[s] = swaddr(smb + 1024, ldrow, ldh * 4 + s);
        bdst[s] = swaddr(smb + 1024 + 16384, ldrow, ldh * 4 + s);
    }

    float d[2][8][4];
#pragma unroll
    for (int i = 0; i < 2; i++)
#pragma unroll
        for (int j = 0; j < 8; j++)
#pragma unroll
            for (int k = 0; k < 4; k++) d[i][j][k] = 0.f;

    auto issue = [&](int c, int buf) {
        const int p = c / 8, kc = (c % 8) * 64;
        const u16* Aarr = (kc < 256) ? ((p == 1) ? fol : foh) : ((p == 1) ? fsl : fsh);
        const int acol = (kc < 256) ? kc : kc - 256;
        const u16* Bsrc = (p == 2) ? gWl : gWh;
        const u16* as = Aarr + (size_t)(m0 + ldrow) * 256 + acol + ldh * 32;
        const u16* bs = Bsrc + (size_t)(n0 + ldrow) * 512 + kc + ldh * 32;
        const uint32_t bo = (uint32_t)(buf * STG);
#pragma unroll
        for (int s = 0; s < 4; s++) cp_async16(adst[s] + bo, as + 8 * s);
#pragma unroll
        for (int s = 0; s < 4; s++) cp_async16(bdst[s] + bo, bs + 8 * s);
        cp_commit();
    };

    const int g8 = lid & 7, grp = lid >> 3;
    const int arow_off = g8 + ((grp & 1) << 3);
    const int acol_sel = grp >> 1;
    const int brow_off = g8 + ((grp >> 1) << 3);
    const int bcol_sel = grp & 1;

    issue(0, 0);
    issue(1, 1);

#pragma unroll 1
    for (int c = 0; c < 24; c++) {
        const int buf = c % 3;
        if (c < 22) cp_wait1(); else cp_wait0();
        __syncthreads();
        if (c + 2 < 24) issue(c + 2, (c + 2) % 3);
        const uint32_t abase = smb + 1024 + buf * STG;
        const uint32_t bbase = abase + 16384;
#pragma unroll
        for (int kt2 = 0; kt2 < 2; kt2++) {
            uint32_t a[2][2][4];
#pragma unroll
            for (int mt = 0; mt < 2; mt++)
#pragma unroll
                for (int kk = 0; kk < 2; kk++) {
                    int kt = 2 * kt2 + kk;
                    ldsm_x4(a[mt][kk][0], a[mt][kk][1], a[mt][kk][2], a[mt][kk][3],
                            swaddr(abase, wm * 32 + mt * 16 + arow_off, 2 * kt + acol_sel));
                }
#pragma unroll
            for (int nt = 0; nt < 4; nt++) {
                uint32_t b[2][4];
#pragma unroll
                for (int kk = 0; kk < 2; kk++) {
                    int kt = 2 * kt2 + kk;
                    ldsm_x4(b[kk][0], b[kk][1], b[kk][2], b[kk][3],
                            swaddr(bbase, wn * 64 + nt * 16 + brow_off, 2 * kt + bcol_sel));
                }
#pragma unroll
                for (int mt = 0; mt < 2; mt++)
#pragma unroll
                    for (int n8 = 0; n8 < 2; n8++)
#pragma unroll
                        for (int kk = 0; kk < 2; kk++)
                            mma_bf16(d[mt][nt * 2 + n8], a[mt][kk], &b[kk][n8 * 2]);
            }
        }
        __syncthreads();
    }

#pragma unroll
    for (int mt = 0; mt < 2; mt++) {
        int r0 = m0 + wm * 32 + mt * 16 + (lid >> 2);
#pragma unroll
        for (int f = 0; f < 8; f++) {
            int n = n0 + wn * 64 + f * 8 + 2 * (lid & 3);
            float2 bv = *(const float2*)(gb + n);
#pragma unroll
            for (int rr = 0; rr < 2; rr++) {
                int r = r0 + rr * 8;
                float2 fov = *(const float2*)(fo + (size_t)r * 256 + n);
                float2 fsv = *(const float2*)(fs + (size_t)r * 256 + n);
                float s0 = sigm(d[mt][f][2 * rr + 0] + bv.x);
                float s1 = sigm(d[mt][f][2 * rr + 1] + bv.y);
                float2 o = {s0 * fov.x + (1.f - s0) * fsv.x,
                            s1 * fov.y + (1.f - s1) * fsv.y};
                *(float2*)(out + (size_t)r * 256 + n) = o;
            }
        }
    }
}

// ---------------- BiLSTM recurrence (lean cluster protocol) ----------------
// Per step: local-half FFMA first (covered by prev-step __syncthreads), then
// acquire-wait on 64 remote arrivals (peer h in flight during local compute),
// then remote-half FFMA. Producers (t<64) release-arrive on the PEER barrier
// only (count=64); local visibility via a second __syncthreads.
__global__ __launch_bounds__(256, 1)
void lstm_k(const float* __restrict__ pwf, const float* __restrict__ pwb,
            const float* __restrict__ Wf,  const float* __restrict__ Wb,
            float* __restrict__ fo,
            const float* __restrict__ psf, const float* __restrict__ psb,
            const float* __restrict__ sWf, const float* __restrict__ sWb,
            float* __restrict__ fs)
{
    __shared__ __align__(16) float h_sh[2][128];
    __shared__ float gacc[256];
    __shared__ __align__(8) ull bars[2];
    const int t = threadIdx.x;
    const int cidg = blockIdx.x >> 1;
    const uint32_t r = ctarank();

    const float *pre, *Whh; float* outb; int L, dir, seq;
    if (cidg < 64) {
        dir = cidg & 1; seq = cidg >> 1;
        pre = dir ? pwb : pwf; Whh = dir ? Wb : Wf; outb = fo; L = 1024;
    } else {
        int c = cidg - 64;
        dir = c & 1; seq = c >> 1;
        pre = dir ? psb : psf; Whh = dir ? sWb : sWf; outb = fs; L = 64;
    }
    const int q = t >> 6, u = t & 63;
    const int grow = q * 128 + (int)r * 64 + u;
    const int rl = (int)r, rp = (int)(r ^ 1u);

    // weight halves: wl = columns of the LOCAL h half, wr_ = peer half
    ull wl[32], wr_[32];
    {
        const ulonglong2* pl = (const ulonglong2*)(Whh + (size_t)grow * 128 + rl * 64);
        const ulonglong2* pr = (const ulonglong2*)(Whh + (size_t)grow * 128 + rp * 64);
#pragma unroll
        for (int i = 0; i < 16; i++) {
            ulonglong2 a = pl[i]; wl[2 * i] = a.x; wl[2 * i + 1] = a.y;
            ulonglong2 b = pr[i]; wr_[2 * i] = b.x; wr_[2 * i + 1] = b.y;
        }
    }
    if (t < 128) { h_sh[0][t] = 0.f; h_sh[1][t] = 0.f; }
    uint32_t bar0 = smem_u32(&bars[0]), bar1 = smem_u32(&bars[1]);
    if (t == 0) { mbar_init(bar0, 64); mbar_init(bar1, 64); }
    __syncthreads();
    cluster_sync_();
    const uint32_t peer = r ^ 1u;
    const uint32_t rbar0 = mapa_u32(bar0, peer), rbar1 = mapa_u32(bar1, peer);
    const uint32_t hb0 = smem_u32(&h_sh[0][0]), hb1 = smem_u32(&h_sh[1][0]);
    const size_t seqbase = (size_t)seq * L;

    int ph0 = 0, ph1 = 0;
    float c = 0.f;
    float pv0 = __ldg(pre + (seqbase + (dir ? (L - 1) : 0)) * 512 + grow);
    float pv1 = (L > 1) ? __ldg(pre + (seqbase + (dir ? (L - 2) : 1)) * 512 + grow) : 0.f;

    for (int s = 0; s < L; s++) {
        int b = s & 1;
        // local-half FFMA first (h_sh local half valid: init or prev-step sync2)
        const ull* hl = (const ull*)&h_sh[b][rl * 64];
        ull l0 = 0ULL, l1 = 0ULL;
#pragma unroll
        for (int k = 0; k < 16; k++) {
            l0 = ffma2(wl[2 * k],     hl[2 * k],     l0);
            l1 = ffma2(wl[2 * k + 1], hl[2 * k + 1], l1);
        }
        // wait for the peer's 64 h values (in flight during local compute)
        if (s > 0) {
            if (b) { mbar_wait(bar1, ph1); ph1 ^= 1; }
            else   { mbar_wait(bar0, ph0); ph0 ^= 1; }
        }
        const ull* hr = (const ull*)&h_sh[b][rp * 64];
        ull m0a = 0ULL, m1a = 0ULL;
#pragma unroll
        for (int k = 0; k < 16; k++) {
            m0a = ffma2(wr_[2 * k],     hr[2 * k],     m0a);
            m1a = ffma2(wr_[2 * k + 1], hr[2 * k + 1], m1a);
        }
        float2 s0 = unpack2(l0), s1 = unpack2(l1), s2 = unpack2(m0a), s3 = unpack2(m1a);
        float acc = pv0 + ((s0.x + s0.y) + (s1.x + s1.y)) + ((s2.x + s2.y) + (s3.x + s3.y));
        pv0 = pv1;
        int sp2 = s + 2;
        pv1 = (sp2 < L) ? __ldg(pre + (seqbase + (dir ? (L - 1 - sp2) : sp2)) * 512 + grow) : 0.f;
        gacc[t] = (q == 2) ? tanh_fast(acc) : sigm(acc);
        __syncthreads();                       // sync1: gacc + reads of h_sh[b] done
        int nb = b ^ 1;
        bool last = (s == L - 1);
        if (t < 64) {
            float gi = gacc[t], gf = gacc[64 + t], gg = gacc[128 + t], go = gacc[192 + t];
            c = gf * c + gi * gg;
            float h = go * tanh_fast(c);
            int j = rl * 64 + t;
            int tp = dir ? (L - 1 - s) : s;
            outb[(seqbase + tp) * 256 + dir * 128 + j] = h;
            if (!last) {
                h_sh[nb][j] = h;
                st_cluster_f32(mapa_u32((nb ? hb1 : hb0) + 4u * j, peer), h);
                mbar_arrive_rel_cluster(nb ? rbar1 : rbar0);   // release covers own st
            }
        }
        __syncthreads();                       // sync2: local h_sh[nb] visible next step
    }
    cluster_sync_();
}

extern "C" void kernel_launch(void* const* d_in, const int* in_sizes, int n_in,
                              void* d_out, int out_size)
{
    (void)in_sizes; (void)out_size;
    const int off = (n_in >= 18) ? 1 : 0;
    const int*   widx   = (const int*)d_in[0];
    const int*   sidx   = (const int*)d_in[1];
    const float* E      = (const float*)d_in[2 + off];
    const float* Wih_f  = (const float*)d_in[3 + off];
    const float* Whh_f  = (const float*)d_in[4 + off];
    const float* b_f    = (const float*)d_in[5 + off];
    const float* Wih_b  = (const float*)d_in[6 + off];
    const float* Whh_b  = (const float*)d_in[7 + off];
    const float* b_b    = (const float*)d_in[8 + off];
    const float* sWih_f = (const float*)d_in[9 + off];
    const float* sWhh_f = (const float*)d_in[10 + off];
    const float* sb_f   = (const float*)d_in[11 + off];
    const float* sWih_b = (const float*)d_in[12 + off];
    const float* sWhh_b = (const float*)d_in[13 + off];
    const float* sb_b   = (const float*)d_in[14 + off];
    const float* gW     = (const float*)d_in[15 + off];
    const float* gb     = (const float*)d_in[16 + off];
    float* out = (float*)d_out;

    float *pwf, *pwb, *psf, *psb, *fo, *fs;
    u16 *eh, *el, *wh, *wl, *foh, *fol, *fsh, *fsl, *gwh, *gwl;
    cudaGetSymbolAddress((void**)&pwf, g_pre_wf);
    cudaGetSymbolAddress((void**)&pwb, g_pre_wb);
    cudaGetSymbolAddress((void**)&psf, g_pre_sf);
    cudaGetSymbolAddress((void**)&psb, g_pre_sb);
    cudaGetSymbolAddress((void**)&fo, g_fo);
    cudaGetSymbolAddress((void**)&fs, g_fs);
    cudaGetSymbolAddress((void**)&eh, g_Eh);
    cudaGetSymbolAddress((void**)&el, g_El);
    cudaGetSymbolAddress((void**)&wh, g_Wh);
    cudaGetSymbolAddress((void**)&wl, g_Wl);
    cudaGetSymbolAddress((void**)&foh, g_foh);
    cudaGetSymbolAddress((void**)&fol, g_fol);
    cudaGetSymbolAddress((void**)&fsh, g_fsh);
    cudaGetSymbolAddress((void**)&fsl, g_fsl);
    cudaGetSymbolAddress((void**)&gwh, g_gWh);
    cudaGetSymbolAddress((void**)&gwl, g_gWl);

    // bf16 hi/lo splits (E, 4 input-proj W, gate W)
    const int n4E = EELEM / 4;
    cvt_split_k<<<(n4E + 255) / 256, 256>>>(E, eh, el, n4E);
    const int n4W = WELEM / 4;
    cvt_split_k<<<(n4W + 255) / 256, 256>>>(Wih_f,  wh + 0 * WELEM, wl + 0 * WELEM, n4W);
    cvt_split_k<<<(n4W + 255) / 256, 256>>>(Wih_b,  wh + 1 * WELEM, wl + 1 * WELEM, n4W);
    cvt_split_k<<<(n4W + 255) / 256, 256>>>(sWih_f, wh + 2 * WELEM, wl + 2 * WELEM, n4W);
    cvt_split_k<<<(n4W + 255) / 256, 256>>>(sWih_b, wh + 3 * WELEM, wl + 3 * WELEM, n4W);
    const int n4G = (256 * 512) / 4;
    cvt_split_k<<<(n4G + 255) / 256, 256>>>(gW, gwh, gwl, n4G);

    // 4 pre-activation GEMMs on HMMA (grid: n fastest for L2 A-reuse)
    TcArgs ta;
    ta.idx[0] = widx; ta.idx[1] = widx; ta.idx[2] = sidx; ta.idx[3] = sidx;
    ta.bias[0] = b_f; ta.bias[1] = b_b; ta.bias[2] = sb_f; ta.bias[3] = sb_b;
    ta.C[0] = pwf;    ta.C[1] = pwb;    ta.C[2] = psf;    ta.C[3] = psb;
    cudaFuncSetAttribute(mma_gemm, cudaFuncAttributeMaxDynamicSharedMemorySize, MG_SMEM);
    mma_gemm<<<dim3(4, MTOK / 128, 4), 256, MG_SMEM>>>(ta, eh, el, wh, wl);

    // merged BiLSTM (word cids first for max overlap of sent backfill)
    {
        cudaLaunchConfig_t cfg = {};
        cfg.gridDim = dim3((64 + 1024) * 2, 1, 1);
        cfg.blockDim = dim3(256, 1, 1);
        cfg.dynamicSmemBytes = 0;
        cfg.stream = 0;
        cudaLaunchAttribute attr[1];
        attr[0].id = cudaLaunchAttributeClusterDimension;
        attr[0].val.clusterDim.x = 2; attr[0].val.clusterDim.y = 1; attr[0].val.clusterDim.z = 1;
        cfg.attrs = attr; cfg.numAttrs = 1;
        cudaLaunchKernelEx(&cfg, lstm_k, (const float*)pwf, (const float*)pwb, Whh_f, Whh_b, fo,
                           (const float*)psf, (const float*)psb, sWhh_f, sWhh_b, fs);
    }

    // fo/fs splits, then gate GEMM + blend on HMMA
    const int n4F = (MTOK * 256) / 4;
    cvt_split_k<<<(n4F + 255) / 256, 256>>>(fo, foh, fol, n4F);
    cvt_split_k<<<(n4F + 255) / 256, 256>>>(fs, fsh, fsl, n4F);
    cudaFuncSetAttribute(gate_mma, cudaFuncAttributeMaxDynamicSharedMemorySize, MG_SMEM);
    gate_mma<<<dim3(2, MTOK / 128, 1), 256, MG_SMEM>>>(foh, fol, fsh, fsl, gwh, gwl, gb, out, fo, fs);
}